// round 11
// baseline (speedup 1.0000x reference)
#include <cuda_runtime.h>
#include <cuda_fp16.h>
#include <cstdint>

// ---------------- problem constants ----------------
#define B   512
#define NN  21
#define II  256
#define HH  1024
#define FH  4096          // 4*HH
#define KK  1280          // II + HH
#define EPS 1e-12f

// ---------------- GEMM tiling ----------------
#define TM 128
#define TN 256
#define TK 32
#define NSTAGE 4
#define NCHUNK (KK / TK)
#define PADB 80

#define A_STAGE_B (TM * PADB)
#define B_STAGE_B (TN * PADB)
#define STAGE_B   (A_STAGE_B + B_STAGE_B)
#define SM_BYTES  (NSTAGE * STAGE_B)

// cvt region sizes in 8-element units
#define N8_WIH (5 * FH * II / 8)
#define N8_WHH (5 * FH * HH / 8)
#define N8_IN  (B * NN * II / 8)
#define N8_HX  (B * NN * HH / 8)
#define N8_TOT (N8_WIH + N8_WHH + N8_IN + N8_HX)
#define CVT_BLOCKS ((N8_TOT + 255) / 256)

// ---------------- scratch ----------------
__device__ __half  g_gates_h[(size_t)B * NN * FH];
__device__ __half2 g_gx2[NN * NN];                 // (w,w) pairs of normalized gx
__device__ __half  g_wih_h[(size_t)5 * FH * II];
__device__ __half  g_whh_h[(size_t)5 * FH * HH];
__device__ __half  g_in_h[(size_t)B * NN * II];
__device__ __half  g_hx_h[(size_t)B * NN * HH];

// ---------------- helpers ----------------
__device__ __forceinline__ uint32_t smem_u32(const void* p) {
    uint32_t a;
    asm("{ .reg .u64 t; cvta.to.shared.u64 t, %1; cvt.u32.u64 %0, t; }" : "=r"(a) : "l"(p));
    return a;
}
__device__ __forceinline__ void cp16(uint32_t saddr, const void* gptr) {
    asm volatile("cp.async.cg.shared.global [%0], [%1], 16;" :: "r"(saddr), "l"(gptr));
}
__device__ __forceinline__ void ldsm4(uint32_t* r, uint32_t saddr) {
    asm volatile("ldmatrix.sync.aligned.m8n8.x4.shared.b16 {%0,%1,%2,%3}, [%4];"
                 : "=r"(r[0]), "=r"(r[1]), "=r"(r[2]), "=r"(r[3]) : "r"(saddr));
}
__device__ __forceinline__ void mma16(float* c, const uint32_t* a, const uint32_t* b) {
    asm volatile(
        "mma.sync.aligned.m16n8k16.row.col.f32.f16.f16.f32 "
        "{%0,%1,%2,%3}, {%4,%5,%6,%7}, {%8,%9}, {%0,%1,%2,%3};"
        : "+f"(c[0]), "+f"(c[1]), "+f"(c[2]), "+f"(c[3])
        : "r"(a[0]), "r"(a[1]), "r"(a[2]), "r"(a[3]), "r"(b[0]), "r"(b[1]));
}
__device__ __forceinline__ float tanh_a(float x) {
    float r;
    asm("tanh.approx.f32 %0, %1;" : "=f"(r) : "f"(x));
    return r;
}
__device__ __forceinline__ float fsig(float x) {
    return fmaf(tanh_a(0.5f * x), 0.5f, 0.5f);   // sigmoid via 1 MUFU
}

// ---------------- kernel: fused fp32->fp16 conversion + gx normalization ----------------
__global__ void cvt_all_kernel(const float4* __restrict__ wih, const float4* __restrict__ whh,
                               const float4* __restrict__ in,  const float4* __restrict__ hx,
                               uint4* __restrict__ o_wih, uint4* __restrict__ o_whh,
                               uint4* __restrict__ o_in,  uint4* __restrict__ o_hx,
                               const float* __restrict__ G, float* __restrict__ gx_out) {
    if (blockIdx.x == CVT_BLOCKS) {
        // ---- gx block ----
        __shared__ float sG[NN * NN];
        __shared__ float den[NN];
        __shared__ float den2[NN];
        int tid = threadIdx.x;
        for (int i = tid; i < NN * NN; i += blockDim.x) sG[i] = G[i];
        __syncthreads();
        if (tid < NN) {
            float s = 0.f;
            for (int j = 0; j < NN; j++) s += fabsf(sG[tid * NN + j]);
            den[tid] = fmaxf(s, EPS);
        }
        __syncthreads();
        for (int i = tid; i < NN * NN; i += blockDim.x) sG[i] = sG[i] / den[i / NN];
        __syncthreads();
        if (tid < NN) {
            float s = 0.f;
            for (int j = 0; j < NN; j++) s += fabsf(sG[tid * NN + j]);
            den2[tid] = fmaxf(s, EPS);
        }
        __syncthreads();
        for (int i = tid; i < NN * NN; i += blockDim.x) {
            float w = sG[i];
            g_gx2[i]  = __float2half2_rn(w);
            gx_out[i] = w / den2[i / NN];
        }
        return;
    }

    int i = blockIdx.x * blockDim.x + threadIdx.x;
    if (i >= N8_TOT) return;
    const float4* s;
    uint4* d;
    int j = i;
    if (j < N8_WIH) { s = wih; d = o_wih; }
    else {
        j -= N8_WIH;
        if (j < N8_WHH) { s = whh; d = o_whh; }
        else {
            j -= N8_WHH;
            if (j < N8_IN) { s = in; d = o_in; }
            else { j -= N8_IN; s = hx; d = o_hx; }
        }
    }
    float4 v0 = s[2 * j];
    float4 v1 = s[2 * j + 1];
    __half2 h0 = __floats2half2_rn(v0.x, v0.y);
    __half2 h1 = __floats2half2_rn(v0.z, v0.w);
    __half2 h2 = __floats2half2_rn(v1.x, v1.y);
    __half2 h3 = __floats2half2_rn(v1.z, v1.w);
    uint4 o;
    o.x = *(uint32_t*)&h0; o.y = *(uint32_t*)&h1;
    o.z = *(uint32_t*)&h2; o.w = *(uint32_t*)&h3;
    d[j] = o;
}

// ---------------- kernel 1: fp16 mma.sync gates GEMM, 512 threads ----------------
__global__ __launch_bounds__(512, 1)
void gates_gemm(const float* __restrict__ bhh, const int* __restrict__ ntypes) {
    extern __shared__ char smc[];
    const int tid  = threadIdx.x;
    const int lane = tid & 31;
    const int wid  = tid >> 5;

    const int n  = blockIdx.z;
    const int bm = blockIdx.y * TM;
    const int bo = blockIdx.x * TN;
    const int nt = ntypes[n];
    const __half* wih = g_wih_h + (size_t)nt * FH * II;
    const __half* whh = g_whh_h + (size_t)nt * FH * HH;

    const uint32_t sb = smem_u32(smc);

    const int wm = (wid & 3) * 32;
    const int wn = (wid >> 2) * 64;

    const uint32_t aL = (uint32_t)((((lane >> 3) & 1) * 8 + (lane & 7)) * PADB + (lane >> 4) * 16);
    const uint32_t bL = (uint32_t)((((lane >> 4) & 1) * 8 + (lane & 7)) * PADB + ((lane >> 3) & 1) * 16);

    float acc[2][8][4];
#pragma unroll
    for (int i = 0; i < 2; i++)
#pragma unroll
        for (int j = 0; j < 8; j++)
#pragma unroll
            for (int v = 0; v < 4; v++) acc[i][j][v] = 0.f;

    auto load_stage = [&](int kt) {
        const int s  = kt % NSTAGE;
        const int k0 = kt * TK;
        const uint32_t ab = sb + (uint32_t)(s * STAGE_B);
        const uint32_t bb = ab + (uint32_t)A_STAGE_B;
        {
            int r = tid >> 2, c = tid & 3;
            int k = k0 + c * 8;
            const __half* src = (k < II)
                ? g_in_h + ((size_t)(bm + r) * NN + n) * II + k
                : g_hx_h + ((size_t)(bm + r) * NN + n) * HH + (k - II);
            cp16(ab + (uint32_t)(r * PADB + c * 16), src);
        }
#pragma unroll
        for (int i = 0; i < 2; i++) {
            int f = tid + i * 512;
            int r = f >> 2, c = f & 3;
            int k = k0 + c * 8;
            const __half* src = (k < II)
                ? wih + (size_t)(bo + r) * II + k
                : whh + (size_t)(bo + r) * HH + (k - II);
            cp16(bb + (uint32_t)(r * PADB + c * 16), src);
        }
    };

#pragma unroll
    for (int s = 0; s < NSTAGE; s++) {
        load_stage(s);
        asm volatile("cp.async.commit_group;" ::: "memory");
    }

    for (int kt = 0; kt < NCHUNK; kt++) {
        asm volatile("cp.async.wait_group %0;" :: "n"(NSTAGE - 1) : "memory");
        __syncthreads();

        const int s = kt % NSTAGE;
        const uint32_t sAb = sb + (uint32_t)(s * STAGE_B);
        const uint32_t sBb = sAb + (uint32_t)A_STAGE_B;

#pragma unroll
        for (int ks = 0; ks < TK / 16; ks++) {
            const uint32_t kb = (uint32_t)(ks * 32);
            uint32_t af[2][4];
#pragma unroll
            for (int mi = 0; mi < 2; mi++)
                ldsm4(af[mi], sAb + (uint32_t)((wm + mi * 16) * PADB) + kb + aL);
            uint32_t bq[4][4];
#pragma unroll
            for (int np = 0; np < 4; np++)
                ldsm4(bq[np], sBb + (uint32_t)((wn + np * 16) * PADB) + kb + bL);
#pragma unroll
            for (int mi = 0; mi < 2; mi++)
#pragma unroll
                for (int ni = 0; ni < 8; ni++)
                    mma16(acc[mi][ni], af[mi], &bq[ni >> 1][(ni & 1) * 2]);
        }
        __syncthreads();
        if (kt + NSTAGE < NCHUNK) load_stage(kt + NSTAGE);
        asm volatile("cp.async.commit_group;" ::: "memory");
    }

    const int lr = lane >> 2;
    const int lq = lane & 3;
    const float* brow = bhh + (size_t)nt * FH + bo;
#pragma unroll
    for (int mi = 0; mi < 2; mi++) {
        int r0 = wm + mi * 16 + lr;
        __half* out0 = g_gates_h + ((size_t)(bm + r0)     * NN + n) * FH + bo;
        __half* out1 = g_gates_h + ((size_t)(bm + r0 + 8) * NN + n) * FH + bo;
#pragma unroll
        for (int ni = 0; ni < 8; ni++) {
            int col = wn + ni * 8 + lq * 2;
            float2 bv = *(const float2*)(brow + col);
            __half2 v0 = __floats2half2_rn(acc[mi][ni][0] + bv.x, acc[mi][ni][1] + bv.y);
            __half2 v1 = __floats2half2_rn(acc[mi][ni][2] + bv.x, acc[mi][ni][3] + bv.y);
            *(__half2*)(out0 + col) = v0;
            *(__half2*)(out1 + col) = v1;
        }
    }
}

// ---------------- kernel 2: graph mix + LSTM; 2 gates per thread, pair exchange ----------------
// thread pair (2p, 2p+1) handles h = {h0, h0+1}; even: (in, cell), odd: (forget, out)
__global__ __launch_bounds__(128)
void pass2(const float* __restrict__ cx, const int* __restrict__ tptr,
           float* __restrict__ hy, float* __restrict__ cyo) {
    __shared__ __half2 sgx[NN * NN];
    const int tid = threadIdx.x;
    for (int i = tid; i < NN * NN; i += 128) sgx[i] = g_gx2[i];
    __syncthreads();

    const int b    = blockIdx.y;
    const int role = tid & 1;                       // 0: (i,c), 1: (f,o)
    const int h    = blockIdx.x * 128 + (tid >> 1) * 2;

    const float t1  = (float)(*tptr) + 1.0f;
    const float ph0 = floorf((float)h       / (float)(HH - 1) * 8.0f + 1.0f);
    const float ph1 = floorf((float)(h + 1) / (float)(HH - 1) * 8.0f + 1.0f);
    const float mk0 = (fmodf(t1, ph0) < 0.01f) ? 1.0f : 0.0f;
    const float mk1 = (fmodf(t1, ph1) < 0.01f) ? 1.0f : 0.0f;

    // role 0 -> planes 0 (in) and 2 (cell); role 1 -> planes 1 (forget) and 3 (out)
    __half2 rgA[NN], rgB[NN];
    const __half* gbase = g_gates_h + (size_t)b * NN * FH + h + role * HH;
#pragma unroll
    for (int nI = 0; nI < NN; nI++) {
        const __half* p = gbase + (size_t)nI * FH;
        rgA[nI] = *(const __half2*)(p);
        rgB[nI] = *(const __half2*)(p + 2 * HH);
    }

#pragma unroll 1
    for (int m = 0; m < NN; m++) {
        const __half2* wrow = &sgx[m * NN];
        __half2 z = __float2half2_rn(0.f);
        __half2 a0 = z, a1 = z, c0 = z, c1 = z;
#pragma unroll
        for (int nI = 0; nI < NN; nI++) {
            __half2 w = wrow[nI];
            if (nI & 1) {
                a1 = __hfma2(w, rgA[nI], a1);
                c1 = __hfma2(w, rgB[nI], c1);
            } else {
                a0 = __hfma2(w, rgA[nI], a0);
                c0 = __hfma2(w, rgB[nI], c0);
            }
        }
        float2 gA = __half22float2(__hadd2(a0, a1));
        float2 gB = __half22float2(__hadd2(c0, c1));

        float vx = 0.f, vy = 0.f;
        if (role == 0) {
            vx = fsig(gA.x) * tanh_a(gB.x);   // ingate * cellgate
            vy = fsig(gA.y) * tanh_a(gB.y);
        }
        float rx = __shfl_xor_sync(0xffffffffu, vx, 1);
        float ry = __shfl_xor_sync(0xffffffffu, vy, 1);

        if (role == 1) {
            size_t idx = ((size_t)b * NN + m) * HH + h;
            float2 cxv = *(const float2*)(cx + idx);
            float fsx = fsig(gA.x), fsy = fsig(gA.y);
            float osx = fsig(gB.x), osy = fsig(gB.y);
            float cyx = mk0 * fmaf(fsx, cxv.x, rx) + (1.f - mk0) * cxv.x;
            float cyy = mk1 * fmaf(fsy, cxv.y, ry) + (1.f - mk1) * cxv.y;
            float hyx = osx * tanh_a(cyx);
            float hyy = osy * tanh_a(cyy);
            *(float2*)(hy + idx)  = make_float2(hyx, hyy);
            *(float2*)(cyo + idx) = make_float2(cyx, cyy);
        }
    }
}

// ---------------- launch ----------------
extern "C" void kernel_launch(void* const* d_in, const int* in_sizes, int n_in,
                              void* d_out, int out_size) {
    const float* input  = (const float*)d_in[0];
    const float* hx     = (const float*)d_in[1];
    const float* cx     = (const float*)d_in[2];
    const float* G      = (const float*)d_in[3];
    const float* wih    = (const float*)d_in[4];
    const float* whh    = (const float*)d_in[5];
    const float* bhh    = (const float*)d_in[6];
    const int*   ntypes = (const int*)d_in[7];
    const int*   tptr   = (const int*)d_in[8];

    float* hy  = (float*)d_out;
    float* cy  = hy + (size_t)B * NN * HH;
    float* gxo = cy + (size_t)B * NN * HH;

    cudaFuncSetAttribute(gates_gemm, cudaFuncAttributeMaxDynamicSharedMemorySize, SM_BYTES);

    void *p_wih, *p_whh, *p_in, *p_hx;
    cudaGetSymbolAddress(&p_wih, g_wih_h);
    cudaGetSymbolAddress(&p_whh, g_whh_h);
    cudaGetSymbolAddress(&p_in,  g_in_h);
    cudaGetSymbolAddress(&p_hx,  g_hx_h);

    cvt_all_kernel<<<CVT_BLOCKS + 1, 256>>>(
        (const float4*)wih, (const float4*)whh, (const float4*)input, (const float4*)hx,
        (uint4*)p_wih, (uint4*)p_whh, (uint4*)p_in, (uint4*)p_hx,
        G, gxo);

    dim3 grid1(FH / TN, B / TM, NN);   // (16, 4, 21)
    gates_gemm<<<grid1, 512, SM_BYTES>>>(bhh, ntypes);

    dim3 grid2(HH / 128, B);           // (8, 512)
    pass2<<<grid2, 128>>>(cx, tptr, hy, cy);
}

// round 12
// speedup vs baseline: 1.0531x; 1.0531x over previous
#include <cuda_runtime.h>
#include <cuda_fp16.h>
#include <cstdint>

// ---------------- problem constants ----------------
#define B   512
#define NN  21
#define II  256
#define HH  1024
#define FH  4096          // 4*HH
#define KK  1280          // II + HH
#define EPS 1e-12f

// ---------------- GEMM tiling ----------------
#define TM 128
#define TN 256
#define TK 32
#define NSTAGE 4
#define NCHUNK (KK / TK)
#define PADB 80

#define A_STAGE_B (TM * PADB)
#define B_STAGE_B (TN * PADB)
#define STAGE_B   (A_STAGE_B + B_STAGE_B)
#define SM_BYTES  (NSTAGE * STAGE_B)

// cvt region sizes in 8-element units
#define N8_WIH (5 * FH * II / 8)
#define N8_WHH (5 * FH * HH / 8)
#define N8_IN  (B * NN * II / 8)
#define N8_HX  (B * NN * HH / 8)
#define N8_TOT (N8_WIH + N8_WHH + N8_IN + N8_HX)
#define CVT_BLOCKS ((N8_TOT + 255) / 256)

// ---------------- scratch ----------------
__device__ __half  g_gates_h[(size_t)B * NN * FH];
__device__ __half2 g_gx2[NN * NN];
__device__ __half  g_wih_h[(size_t)5 * FH * II];
__device__ __half  g_whh_h[(size_t)5 * FH * HH];
__device__ __half  g_in_h[(size_t)B * NN * II];
__device__ __half  g_hx_h[(size_t)B * NN * HH];

// ---------------- helpers ----------------
__device__ __forceinline__ uint32_t smem_u32(const void* p) {
    uint32_t a;
    asm("{ .reg .u64 t; cvta.to.shared.u64 t, %1; cvt.u32.u64 %0, t; }" : "=r"(a) : "l"(p));
    return a;
}
__device__ __forceinline__ void cp16(uint32_t saddr, const void* gptr) {
    asm volatile("cp.async.cg.shared.global [%0], [%1], 16;" :: "r"(saddr), "l"(gptr));
}
__device__ __forceinline__ void ldsm4(uint32_t* r, uint32_t saddr) {
    asm volatile("ldmatrix.sync.aligned.m8n8.x4.shared.b16 {%0,%1,%2,%3}, [%4];"
                 : "=r"(r[0]), "=r"(r[1]), "=r"(r[2]), "=r"(r[3]) : "r"(saddr));
}
__device__ __forceinline__ void mma16(float* c, const uint32_t* a, const uint32_t* b) {
    asm volatile(
        "mma.sync.aligned.m16n8k16.row.col.f32.f16.f16.f32 "
        "{%0,%1,%2,%3}, {%4,%5,%6,%7}, {%8,%9}, {%0,%1,%2,%3};"
        : "+f"(c[0]), "+f"(c[1]), "+f"(c[2]), "+f"(c[3])
        : "r"(a[0]), "r"(a[1]), "r"(a[2]), "r"(a[3]), "r"(b[0]), "r"(b[1]));
}
__device__ __forceinline__ float tanh_a(float x) {
    float r;
    asm("tanh.approx.f32 %0, %1;" : "=f"(r) : "f"(x));
    return r;
}
__device__ __forceinline__ float fsig(float x) {
    return fmaf(tanh_a(0.5f * x), 0.5f, 0.5f);
}

// ---------------- kernel: fused fp32->fp16 conversion + gx normalization ----------------
__global__ void cvt_all_kernel(const float4* __restrict__ wih, const float4* __restrict__ whh,
                               const float4* __restrict__ in,  const float4* __restrict__ hx,
                               uint4* __restrict__ o_wih, uint4* __restrict__ o_whh,
                               uint4* __restrict__ o_in,  uint4* __restrict__ o_hx,
                               const float* __restrict__ G, float* __restrict__ gx_out) {
    if (blockIdx.x == CVT_BLOCKS) {
        __shared__ float sG[NN * NN];
        __shared__ float den[NN];
        __shared__ float den2[NN];
        int tid = threadIdx.x;
        for (int i = tid; i < NN * NN; i += blockDim.x) sG[i] = G[i];
        __syncthreads();
        if (tid < NN) {
            float s = 0.f;
            for (int j = 0; j < NN; j++) s += fabsf(sG[tid * NN + j]);
            den[tid] = fmaxf(s, EPS);
        }
        __syncthreads();
        for (int i = tid; i < NN * NN; i += blockDim.x) sG[i] = sG[i] / den[i / NN];
        __syncthreads();
        if (tid < NN) {
            float s = 0.f;
            for (int j = 0; j < NN; j++) s += fabsf(sG[tid * NN + j]);
            den2[tid] = fmaxf(s, EPS);
        }
        __syncthreads();
        for (int i = tid; i < NN * NN; i += blockDim.x) {
            float w = sG[i];
            g_gx2[i]  = __float2half2_rn(w);
            gx_out[i] = w / den2[i / NN];
        }
        return;
    }

    int i = blockIdx.x * blockDim.x + threadIdx.x;
    if (i >= N8_TOT) return;
    const float4* s;
    uint4* d;
    int j = i;
    if (j < N8_WIH) { s = wih; d = o_wih; }
    else {
        j -= N8_WIH;
        if (j < N8_WHH) { s = whh; d = o_whh; }
        else {
            j -= N8_WHH;
            if (j < N8_IN) { s = in; d = o_in; }
            else { j -= N8_IN; s = hx; d = o_hx; }
        }
    }
    float4 v0 = s[2 * j];
    float4 v1 = s[2 * j + 1];
    __half2 h0 = __floats2half2_rn(v0.x, v0.y);
    __half2 h1 = __floats2half2_rn(v0.z, v0.w);
    __half2 h2 = __floats2half2_rn(v1.x, v1.y);
    __half2 h3 = __floats2half2_rn(v1.z, v1.w);
    uint4 o;
    o.x = *(uint32_t*)&h0; o.y = *(uint32_t*)&h1;
    o.z = *(uint32_t*)&h2; o.w = *(uint32_t*)&h3;
    d[j] = o;
}

// ---------------- kernel 1: fp16 mma.sync gates GEMM, 512 threads ----------------
__global__ __launch_bounds__(512, 1)
void gates_gemm(const float* __restrict__ bhh, const int* __restrict__ ntypes) {
    extern __shared__ char smc[];
    const int tid  = threadIdx.x;
    const int lane = tid & 31;
    const int wid  = tid >> 5;

    const int n  = blockIdx.z;
    const int bm = blockIdx.y * TM;
    const int bo = blockIdx.x * TN;
    const int nt = ntypes[n];
    const __half* wih = g_wih_h + (size_t)nt * FH * II;
    const __half* whh = g_whh_h + (size_t)nt * FH * HH;

    const uint32_t sb = smem_u32(smc);

    const int wm = (wid & 3) * 32;
    const int wn = (wid >> 2) * 64;

    const uint32_t aL = (uint32_t)((((lane >> 3) & 1) * 8 + (lane & 7)) * PADB + (lane >> 4) * 16);
    const uint32_t bL = (uint32_t)((((lane >> 4) & 1) * 8 + (lane & 7)) * PADB + ((lane >> 3) & 1) * 16);

    float acc[2][8][4];
#pragma unroll
    for (int i = 0; i < 2; i++)
#pragma unroll
        for (int j = 0; j < 8; j++)
#pragma unroll
            for (int v = 0; v < 4; v++) acc[i][j][v] = 0.f;

    auto load_stage = [&](int kt) {
        const int s  = kt % NSTAGE;
        const int k0 = kt * TK;
        const uint32_t ab = sb + (uint32_t)(s * STAGE_B);
        const uint32_t bb = ab + (uint32_t)A_STAGE_B;
        {
            int r = tid >> 2, c = tid & 3;
            int k = k0 + c * 8;
            const __half* src = (k < II)
                ? g_in_h + ((size_t)(bm + r) * NN + n) * II + k
                : g_hx_h + ((size_t)(bm + r) * NN + n) * HH + (k - II);
            cp16(ab + (uint32_t)(r * PADB + c * 16), src);
        }
#pragma unroll
        for (int i = 0; i < 2; i++) {
            int f = tid + i * 512;
            int r = f >> 2, c = f & 3;
            int k = k0 + c * 8;
            const __half* src = (k < II)
                ? wih + (size_t)(bo + r) * II + k
                : whh + (size_t)(bo + r) * HH + (k - II);
            cp16(bb + (uint32_t)(r * PADB + c * 16), src);
        }
    };

#pragma unroll
    for (int s = 0; s < NSTAGE; s++) {
        load_stage(s);
        asm volatile("cp.async.commit_group;" ::: "memory");
    }

    for (int kt = 0; kt < NCHUNK; kt++) {
        asm volatile("cp.async.wait_group %0;" :: "n"(NSTAGE - 1) : "memory");
        __syncthreads();

        const int s = kt % NSTAGE;
        const uint32_t sAb = sb + (uint32_t)(s * STAGE_B);
        const uint32_t sBb = sAb + (uint32_t)A_STAGE_B;

#pragma unroll
        for (int ks = 0; ks < TK / 16; ks++) {
            const uint32_t kb = (uint32_t)(ks * 32);
            uint32_t af[2][4];
#pragma unroll
            for (int mi = 0; mi < 2; mi++)
                ldsm4(af[mi], sAb + (uint32_t)((wm + mi * 16) * PADB) + kb + aL);
            uint32_t bq[4][4];
#pragma unroll
            for (int np = 0; np < 4; np++)
                ldsm4(bq[np], sBb + (uint32_t)((wn + np * 16) * PADB) + kb + bL);
#pragma unroll
            for (int mi = 0; mi < 2; mi++)
#pragma unroll
                for (int ni = 0; ni < 8; ni++)
                    mma16(acc[mi][ni], af[mi], &bq[ni >> 1][(ni & 1) * 2]);
        }
        __syncthreads();
        if (kt + NSTAGE < NCHUNK) load_stage(kt + NSTAGE);
        asm volatile("cp.async.commit_group;" ::: "memory");
    }

    const int lr = lane >> 2;
    const int lq = lane & 3;
    const float* brow = bhh + (size_t)nt * FH + bo;
#pragma unroll
    for (int mi = 0; mi < 2; mi++) {
        int r0 = wm + mi * 16 + lr;
        __half* out0 = g_gates_h + ((size_t)(bm + r0)     * NN + n) * FH + bo;
        __half* out1 = g_gates_h + ((size_t)(bm + r0 + 8) * NN + n) * FH + bo;
#pragma unroll
        for (int ni = 0; ni < 8; ni++) {
            int col = wn + ni * 8 + lq * 2;
            float2 bv = *(const float2*)(brow + col);
            __half2 v0 = __floats2half2_rn(acc[mi][ni][0] + bv.x, acc[mi][ni][1] + bv.y);
            __half2 v1 = __floats2half2_rn(acc[mi][ni][2] + bv.x, acc[mi][ni][3] + bv.y);
            *(__half2*)(out0 + col) = v0;
            *(__half2*)(out1 + col) = v1;
        }
    }
}

// ---------------- kernel 2: graph mix + LSTM; clockwork-mask dead-gate skipping ----------------
__global__ __launch_bounds__(128)
void pass2(const float* __restrict__ cx, const int* __restrict__ tptr,
           float* __restrict__ hy, float* __restrict__ cyo) {
    __shared__ __half2 sgx[NN * NN];
    const int tid = threadIdx.x;
    for (int i = tid; i < NN * NN; i += 128) sgx[i] = g_gx2[i];
    __syncthreads();

    const int b = blockIdx.y;
    const int h = blockIdx.x * 256 + tid * 2;   // this thread: h, h+1

    const float t1  = (float)(*tptr) + 1.0f;
    const float ph0 = floorf((float)h       / (float)(HH - 1) * 8.0f + 1.0f);
    const float ph1 = floorf((float)(h + 1) / (float)(HH - 1) * 8.0f + 1.0f);
    const float mk0 = (fmodf(t1, ph0) < 0.01f) ? 1.0f : 0.0f;
    const float mk1 = (fmodf(t1, ph1) < 0.01f) ? 1.0f : 0.0f;
    const bool  active = (mk0 + mk1) > 0.f;     // warp-uniform (128-h phase blocks)

    const __half* gbase = g_gates_h + (size_t)b * NN * FH + h;

    // outgate fragments always needed
    __half2 rg3[NN];
#pragma unroll
    for (int nI = 0; nI < NN; nI++)
        rg3[nI] = *(const __half2*)(gbase + (size_t)nI * FH + 3 * HH);

    if (active) {
        // full path: also need in/forget/cell gates
        __half2 rg0[NN], rg1[NN], rg2[NN];
#pragma unroll
        for (int nI = 0; nI < NN; nI++) {
            const __half* p = gbase + (size_t)nI * FH;
            rg0[nI] = *(const __half2*)(p);
            rg1[nI] = *(const __half2*)(p + HH);
            rg2[nI] = *(const __half2*)(p + 2 * HH);
        }
#pragma unroll 1
        for (int m = 0; m < NN; m++) {
            const __half2* wrow = &sgx[m * NN];
            __half2 z = __float2half2_rn(0.f);
            __half2 i0 = z, i1 = z, f0 = z, f1 = z, c0 = z, c1 = z, o0 = z, o1 = z;
#pragma unroll
            for (int nI = 0; nI < NN; nI++) {
                __half2 w = wrow[nI];
                if (nI & 1) {
                    i1 = __hfma2(w, rg0[nI], i1);
                    f1 = __hfma2(w, rg1[nI], f1);
                    c1 = __hfma2(w, rg2[nI], c1);
                    o1 = __hfma2(w, rg3[nI], o1);
                } else {
                    i0 = __hfma2(w, rg0[nI], i0);
                    f0 = __hfma2(w, rg1[nI], f0);
                    c0 = __hfma2(w, rg2[nI], c0);
                    o0 = __hfma2(w, rg3[nI], o0);
                }
            }
            float2 ig = __half22float2(__hadd2(i0, i1));
            float2 fg = __half22float2(__hadd2(f0, f1));
            float2 cg = __half22float2(__hadd2(c0, c1));
            float2 og = __half22float2(__hadd2(o0, o1));

            size_t idx = ((size_t)b * NN + m) * HH + h;
            float2 cxv = *(const float2*)(cx + idx);

            float isx = fsig(ig.x), isy = fsig(ig.y);
            float fsx = fsig(fg.x), fsy = fsig(fg.y);
            float ctx = tanh_a(cg.x), cty = tanh_a(cg.y);
            float osx = fsig(og.x), osy = fsig(og.y);

            float cyx = mk0 * (fsx * cxv.x + isx * ctx) + (1.0f - mk0) * cxv.x;
            float cyy = mk1 * (fsy * cxv.y + isy * cty) + (1.0f - mk1) * cxv.y;
            float hyx = osx * tanh_a(cyx);
            float hyy = osy * tanh_a(cyy);

            *(float2*)(hy + idx)  = make_float2(hyx, hyy);
            *(float2*)(cyo + idx) = make_float2(cyx, cyy);
        }
    } else {
        // mask=0 path: cy = cx; hy = sigmoid(outgate_mix) * tanh(cx)
#pragma unroll 1
        for (int m = 0; m < NN; m++) {
            const __half2* wrow = &sgx[m * NN];
            __half2 z = __float2half2_rn(0.f);
            __half2 o0 = z, o1 = z;
#pragma unroll
            for (int nI = 0; nI < NN; nI++) {
                __half2 w = wrow[nI];
                if (nI & 1) o1 = __hfma2(w, rg3[nI], o1);
                else        o0 = __hfma2(w, rg3[nI], o0);
            }
            float2 og = __half22float2(__hadd2(o0, o1));

            size_t idx = ((size_t)b * NN + m) * HH + h;
            float2 cxv = *(const float2*)(cx + idx);

            float hyx = fsig(og.x) * tanh_a(cxv.x);
            float hyy = fsig(og.y) * tanh_a(cxv.y);

            *(float2*)(hy + idx)  = make_float2(hyx, hyy);
            *(float2*)(cyo + idx) = cxv;
        }
    }
}

// ---------------- launch ----------------
extern "C" void kernel_launch(void* const* d_in, const int* in_sizes, int n_in,
                              void* d_out, int out_size) {
    const float* input  = (const float*)d_in[0];
    const float* hx     = (const float*)d_in[1];
    const float* cx     = (const float*)d_in[2];
    const float* G      = (const float*)d_in[3];
    const float* wih    = (const float*)d_in[4];
    const float* whh    = (const float*)d_in[5];
    const float* bhh    = (const float*)d_in[6];
    const int*   ntypes = (const int*)d_in[7];
    const int*   tptr   = (const int*)d_in[8];

    float* hy  = (float*)d_out;
    float* cy  = hy + (size_t)B * NN * HH;
    float* gxo = cy + (size_t)B * NN * HH;

    cudaFuncSetAttribute(gates_gemm, cudaFuncAttributeMaxDynamicSharedMemorySize, SM_BYTES);

    void *p_wih, *p_whh, *p_in, *p_hx;
    cudaGetSymbolAddress(&p_wih, g_wih_h);
    cudaGetSymbolAddress(&p_whh, g_whh_h);
    cudaGetSymbolAddress(&p_in,  g_in_h);
    cudaGetSymbolAddress(&p_hx,  g_hx_h);

    cvt_all_kernel<<<CVT_BLOCKS + 1, 256>>>(
        (const float4*)wih, (const float4*)whh, (const float4*)input, (const float4*)hx,
        (uint4*)p_wih, (uint4*)p_whh, (uint4*)p_in, (uint4*)p_hx,
        G, gxo);

    dim3 grid1(FH / TN, B / TM, NN);   // (16, 4, 21)
    gates_gemm<<<grid1, 512, SM_BYTES>>>(bhh, ntypes);

    dim3 grid2(HH / 256, B);           // (4, 512)
    pass2<<<grid2, 128>>>(cx, tptr, hy, cy);
}

// round 13
// speedup vs baseline: 1.4474x; 1.3744x over previous
#include <cuda_runtime.h>
#include <cuda_fp16.h>
#include <cstdint>

// ---------------- problem constants ----------------
#define B   512
#define NN  21
#define II  256
#define HH  1024
#define FH  4096          // 4*HH
#define KK  1280          // II + HH
#define EPS 1e-12f

// ---------------- GEMM tiling ----------------
#define TM 128
#define TN 256
#define TK 32
#define NSTAGE 4
#define NCHUNK (KK / TK)
#define PADB 80

#define A_STAGE_B (TM * PADB)
#define B_STAGE_B (TN * PADB)
#define STAGE_B   (A_STAGE_B + B_STAGE_B)
#define SM_BYTES  (NSTAGE * STAGE_B)

// cvt region sizes in 8-element units
#define N8_WIH (5 * FH * II / 8)
#define N8_WHH (5 * FH * HH / 8)
#define N8_IN  (B * NN * II / 8)
#define N8_HX  (B * NN * HH / 8)
#define N8_TOT (N8_WIH + N8_WHH + N8_IN + N8_HX)
#define CVT_BLOCKS ((N8_TOT + 255) / 256)

// ---------------- scratch ----------------
__device__ __half  g_gates_h[(size_t)B * NN * FH];
__device__ __half2 g_gx2[NN * NN];
__device__ __half  g_wih_h[(size_t)5 * FH * II];
__device__ __half  g_whh_h[(size_t)5 * FH * HH];
__device__ __half  g_in_h[(size_t)B * NN * II];
__device__ __half  g_hx_h[(size_t)B * NN * HH];

// ---------------- helpers ----------------
__device__ __forceinline__ uint32_t smem_u32(const void* p) {
    uint32_t a;
    asm("{ .reg .u64 t; cvta.to.shared.u64 t, %1; cvt.u32.u64 %0, t; }" : "=r"(a) : "l"(p));
    return a;
}
__device__ __forceinline__ void cp16(uint32_t saddr, const void* gptr) {
    asm volatile("cp.async.cg.shared.global [%0], [%1], 16;" :: "r"(saddr), "l"(gptr));
}
__device__ __forceinline__ void ldsm4(uint32_t* r, uint32_t saddr) {
    asm volatile("ldmatrix.sync.aligned.m8n8.x4.shared.b16 {%0,%1,%2,%3}, [%4];"
                 : "=r"(r[0]), "=r"(r[1]), "=r"(r[2]), "=r"(r[3]) : "r"(saddr));
}
__device__ __forceinline__ void mma16(float* c, const uint32_t* a, const uint32_t* b) {
    asm volatile(
        "mma.sync.aligned.m16n8k16.row.col.f32.f16.f16.f32 "
        "{%0,%1,%2,%3}, {%4,%5,%6,%7}, {%8,%9}, {%0,%1,%2,%3};"
        : "+f"(c[0]), "+f"(c[1]), "+f"(c[2]), "+f"(c[3])
        : "r"(a[0]), "r"(a[1]), "r"(a[2]), "r"(a[3]), "r"(b[0]), "r"(b[1]));
}
__device__ __forceinline__ float tanh_a(float x) {
    float r;
    asm("tanh.approx.f32 %0, %1;" : "=f"(r) : "f"(x));
    return r;
}
__device__ __forceinline__ float fsig(float x) {
    return fmaf(tanh_a(0.5f * x), 0.5f, 0.5f);
}
// exact same phase/mask formula everywhere
__device__ __forceinline__ float phase_of(int h) {
    return floorf((float)h / (float)(HH - 1) * 8.0f + 1.0f);
}
// does the 256-h block starting at h0 contain ANY mask=1 position?
__device__ __forceinline__ bool block_active(int h0, float t1) {
    int p0 = (int)phase_of(h0);
    int h1 = h0 + 255; if (h1 > HH - 1) h1 = HH - 1;
    int p1 = (int)phase_of(h1);
#pragma unroll 4
    for (int p = p0; p <= p1; p++)
        if (fmodf(t1, (float)p) < 0.01f) return true;
    return false;
}

// ---------------- kernel: fused fp32->fp16 conversion + gx normalization ----------------
__global__ void cvt_all_kernel(const float4* __restrict__ wih, const float4* __restrict__ whh,
                               const float4* __restrict__ in,  const float4* __restrict__ hx,
                               uint4* __restrict__ o_wih, uint4* __restrict__ o_whh,
                               uint4* __restrict__ o_in,  uint4* __restrict__ o_hx,
                               const float* __restrict__ G, float* __restrict__ gx_out,
                               const int* __restrict__ tptr) {
    if (blockIdx.x == CVT_BLOCKS) {
        __shared__ float sG[NN * NN];
        __shared__ float den[NN];
        __shared__ float den2[NN];
        int tid = threadIdx.x;
        for (int i = tid; i < NN * NN; i += blockDim.x) sG[i] = G[i];
        __syncthreads();
        if (tid < NN) {
            float s = 0.f;
            for (int j = 0; j < NN; j++) s += fabsf(sG[tid * NN + j]);
            den[tid] = fmaxf(s, EPS);
        }
        __syncthreads();
        for (int i = tid; i < NN * NN; i += blockDim.x) sG[i] = sG[i] / den[i / NN];
        __syncthreads();
        if (tid < NN) {
            float s = 0.f;
            for (int j = 0; j < NN; j++) s += fabsf(sG[tid * NN + j]);
            den2[tid] = fmaxf(s, EPS);
        }
        __syncthreads();
        for (int i = tid; i < NN * NN; i += blockDim.x) {
            float w = sG[i];
            g_gx2[i]  = __float2half2_rn(w);
            gx_out[i] = w / den2[i / NN];
        }
        return;
    }

    int i = blockIdx.x * blockDim.x + threadIdx.x;
    if (i >= N8_TOT) return;
    const float t1 = (float)(*tptr) + 1.0f;
    const float4* s;
    uint4* d;
    int j = i;
    if (j < N8_WIH) {
        // weight row: o_local = (j/32) % FH  (II=256 -> 32 j-units per row)
        int ol = (j >> 5) & (FH - 1);
        int gate = ol >> 10;
        if (gate != 3 && !block_active((ol & 1023) & ~255, t1)) return;  // dead row
        s = wih; d = o_wih;
    } else {
        j -= N8_WIH;
        if (j < N8_WHH) {
            // o_local = (j/128) % FH  (HH=1024 -> 128 j-units per row)
            int ol = (j >> 7) & (FH - 1);
            int gate = ol >> 10;
            if (gate != 3 && !block_active((ol & 1023) & ~255, t1)) return;
            s = whh; d = o_whh;
        } else {
            j -= N8_WHH;
            if (j < N8_IN) { s = in; d = o_in; }
            else { j -= N8_IN; s = hx; d = o_hx; }
        }
    }
    float4 v0 = s[2 * j];
    float4 v1 = s[2 * j + 1];
    __half2 h0 = __floats2half2_rn(v0.x, v0.y);
    __half2 h1 = __floats2half2_rn(v0.z, v0.w);
    __half2 h2 = __floats2half2_rn(v1.x, v1.y);
    __half2 h3 = __floats2half2_rn(v1.z, v1.w);
    uint4 o;
    o.x = *(uint32_t*)&h0; o.y = *(uint32_t*)&h1;
    o.z = *(uint32_t*)&h2; o.w = *(uint32_t*)&h3;
    d[j] = o;
}

// ---------------- kernel 1: fp16 mma.sync gates GEMM, 512 threads, dead-block skip ----------------
__global__ __launch_bounds__(512, 1)
void gates_gemm(const float* __restrict__ bhh, const int* __restrict__ ntypes,
                const int* __restrict__ tptr) {
    const int bo = blockIdx.x * TN;
    {
        // clockwork dead-column skip: CTA covers one gate x one 256-h block
        const float t1 = (float)(*tptr) + 1.0f;
        const int gate = bo >> 10;
        if (gate != 3 && !block_active(bo & 1023, t1)) return;  // uniform exit
    }

    extern __shared__ char smc[];
    const int tid  = threadIdx.x;
    const int lane = tid & 31;
    const int wid  = tid >> 5;

    const int n  = blockIdx.z;
    const int bm = blockIdx.y * TM;
    const int nt = ntypes[n];
    const __half* wih = g_wih_h + (size_t)nt * FH * II;
    const __half* whh = g_whh_h + (size_t)nt * FH * HH;

    const uint32_t sb = smem_u32(smc);

    const int wm = (wid & 3) * 32;
    const int wn = (wid >> 2) * 64;

    const uint32_t aL = (uint32_t)((((lane >> 3) & 1) * 8 + (lane & 7)) * PADB + (lane >> 4) * 16);
    const uint32_t bL = (uint32_t)((((lane >> 4) & 1) * 8 + (lane & 7)) * PADB + ((lane >> 3) & 1) * 16);

    float acc[2][8][4];
#pragma unroll
    for (int i = 0; i < 2; i++)
#pragma unroll
        for (int j = 0; j < 8; j++)
#pragma unroll
            for (int v = 0; v < 4; v++) acc[i][j][v] = 0.f;

    auto load_stage = [&](int kt) {
        const int s  = kt % NSTAGE;
        const int k0 = kt * TK;
        const uint32_t ab = sb + (uint32_t)(s * STAGE_B);
        const uint32_t bb = ab + (uint32_t)A_STAGE_B;
        {
            int r = tid >> 2, c = tid & 3;
            int k = k0 + c * 8;
            const __half* src = (k < II)
                ? g_in_h + ((size_t)(bm + r) * NN + n) * II + k
                : g_hx_h + ((size_t)(bm + r) * NN + n) * HH + (k - II);
            cp16(ab + (uint32_t)(r * PADB + c * 16), src);
        }
#pragma unroll
        for (int i = 0; i < 2; i++) {
            int f = tid + i * 512;
            int r = f >> 2, c = f & 3;
            int k = k0 + c * 8;
            const __half* src = (k < II)
                ? wih + (size_t)(bo + r) * II + k
                : whh + (size_t)(bo + r) * HH + (k - II);
            cp16(bb + (uint32_t)(r * PADB + c * 16), src);
        }
    };

#pragma unroll
    for (int s = 0; s < NSTAGE; s++) {
        load_stage(s);
        asm volatile("cp.async.commit_group;" ::: "memory");
    }

    for (int kt = 0; kt < NCHUNK; kt++) {
        asm volatile("cp.async.wait_group %0;" :: "n"(NSTAGE - 1) : "memory");
        __syncthreads();

        const int s = kt % NSTAGE;
        const uint32_t sAb = sb + (uint32_t)(s * STAGE_B);
        const uint32_t sBb = sAb + (uint32_t)A_STAGE_B;

#pragma unroll
        for (int ks = 0; ks < TK / 16; ks++) {
            const uint32_t kb = (uint32_t)(ks * 32);
            uint32_t af[2][4];
#pragma unroll
            for (int mi = 0; mi < 2; mi++)
                ldsm4(af[mi], sAb + (uint32_t)((wm + mi * 16) * PADB) + kb + aL);
            uint32_t bq[4][4];
#pragma unroll
            for (int np = 0; np < 4; np++)
                ldsm4(bq[np], sBb + (uint32_t)((wn + np * 16) * PADB) + kb + bL);
#pragma unroll
            for (int mi = 0; mi < 2; mi++)
#pragma unroll
                for (int ni = 0; ni < 8; ni++)
                    mma16(acc[mi][ni], af[mi], &bq[ni >> 1][(ni & 1) * 2]);
        }
        __syncthreads();
        if (kt + NSTAGE < NCHUNK) load_stage(kt + NSTAGE);
        asm volatile("cp.async.commit_group;" ::: "memory");
    }

    const int lr = lane >> 2;
    const int lq = lane & 3;
    const float* brow = bhh + (size_t)nt * FH + bo;
#pragma unroll
    for (int mi = 0; mi < 2; mi++) {
        int r0 = wm + mi * 16 + lr;
        __half* out0 = g_gates_h + ((size_t)(bm + r0)     * NN + n) * FH + bo;
        __half* out1 = g_gates_h + ((size_t)(bm + r0 + 8) * NN + n) * FH + bo;
#pragma unroll
        for (int ni = 0; ni < 8; ni++) {
            int col = wn + ni * 8 + lq * 2;
            float2 bv = *(const float2*)(brow + col);
            __half2 v0 = __floats2half2_rn(acc[mi][ni][0] + bv.x, acc[mi][ni][1] + bv.y);
            __half2 v1 = __floats2half2_rn(acc[mi][ni][2] + bv.x, acc[mi][ni][3] + bv.y);
            *(__half2*)(out0 + col) = v0;
            *(__half2*)(out1 + col) = v1;
        }
    }
}

// ---------------- kernel 2: graph mix + LSTM; clockwork-mask dead-gate skipping ----------------
__global__ __launch_bounds__(128)
void pass2(const float* __restrict__ cx, const int* __restrict__ tptr,
           float* __restrict__ hy, float* __restrict__ cyo) {
    __shared__ __half2 sgx[NN * NN];
    const int tid = threadIdx.x;
    for (int i = tid; i < NN * NN; i += 128) sgx[i] = g_gx2[i];
    __syncthreads();

    const int b = blockIdx.y;
    const int h = blockIdx.x * 256 + tid * 2;

    const float t1  = (float)(*tptr) + 1.0f;
    const float ph0 = phase_of(h);
    const float ph1 = phase_of(h + 1);
    const float mk0 = (fmodf(t1, ph0) < 0.01f) ? 1.0f : 0.0f;
    const float mk1 = (fmodf(t1, ph1) < 0.01f) ? 1.0f : 0.0f;
    const bool  active = (mk0 + mk1) > 0.f;

    const __half* gbase = g_gates_h + (size_t)b * NN * FH + h;

    __half2 rg3[NN];
#pragma unroll
    for (int nI = 0; nI < NN; nI++)
        rg3[nI] = *(const __half2*)(gbase + (size_t)nI * FH + 3 * HH);

    if (active) {
        __half2 rg0[NN], rg1[NN], rg2[NN];
#pragma unroll
        for (int nI = 0; nI < NN; nI++) {
            const __half* p = gbase + (size_t)nI * FH;
            rg0[nI] = *(const __half2*)(p);
            rg1[nI] = *(const __half2*)(p + HH);
            rg2[nI] = *(const __half2*)(p + 2 * HH);
        }
#pragma unroll 1
        for (int m = 0; m < NN; m++) {
            const __half2* wrow = &sgx[m * NN];
            __half2 z = __float2half2_rn(0.f);
            __half2 i0 = z, i1 = z, f0 = z, f1 = z, c0 = z, c1 = z, o0 = z, o1 = z;
#pragma unroll
            for (int nI = 0; nI < NN; nI++) {
                __half2 w = wrow[nI];
                if (nI & 1) {
                    i1 = __hfma2(w, rg0[nI], i1);
                    f1 = __hfma2(w, rg1[nI], f1);
                    c1 = __hfma2(w, rg2[nI], c1);
                    o1 = __hfma2(w, rg3[nI], o1);
                } else {
                    i0 = __hfma2(w, rg0[nI], i0);
                    f0 = __hfma2(w, rg1[nI], f0);
                    c0 = __hfma2(w, rg2[nI], c0);
                    o0 = __hfma2(w, rg3[nI], o0);
                }
            }
            float2 ig = __half22float2(__hadd2(i0, i1));
            float2 fg = __half22float2(__hadd2(f0, f1));
            float2 cg = __half22float2(__hadd2(c0, c1));
            float2 og = __half22float2(__hadd2(o0, o1));

            size_t idx = ((size_t)b * NN + m) * HH + h;
            float2 cxv = *(const float2*)(cx + idx);

            float isx = fsig(ig.x), isy = fsig(ig.y);
            float fsx = fsig(fg.x), fsy = fsig(fg.y);
            float ctx = tanh_a(cg.x), cty = tanh_a(cg.y);
            float osx = fsig(og.x), osy = fsig(og.y);

            float cyx = mk0 * (fsx * cxv.x + isx * ctx) + (1.0f - mk0) * cxv.x;
            float cyy = mk1 * (fsy * cxv.y + isy * cty) + (1.0f - mk1) * cxv.y;
            float hyx = osx * tanh_a(cyx);
            float hyy = osy * tanh_a(cyy);

            *(float2*)(hy + idx)  = make_float2(hyx, hyy);
            *(float2*)(cyo + idx) = make_float2(cyx, cyy);
        }
    } else {
#pragma unroll 1
        for (int m = 0; m < NN; m++) {
            const __half2* wrow = &sgx[m * NN];
            __half2 z = __float2half2_rn(0.f);
            __half2 o0 = z, o1 = z;
#pragma unroll
            for (int nI = 0; nI < NN; nI++) {
                __half2 w = wrow[nI];
                if (nI & 1) o1 = __hfma2(w, rg3[nI], o1);
                else        o0 = __hfma2(w, rg3[nI], o0);
            }
            float2 og = __half22float2(__hadd2(o0, o1));

            size_t idx = ((size_t)b * NN + m) * HH + h;
            float2 cxv = *(const float2*)(cx + idx);

            float hyx = fsig(og.x) * tanh_a(cxv.x);
            float hyy = fsig(og.y) * tanh_a(cxv.y);

            *(float2*)(hy + idx)  = make_float2(hyx, hyy);
            *(float2*)(cyo + idx) = cxv;
        }
    }
}

// ---------------- launch ----------------
extern "C" void kernel_launch(void* const* d_in, const int* in_sizes, int n_in,
                              void* d_out, int out_size) {
    const float* input  = (const float*)d_in[0];
    const float* hx     = (const float*)d_in[1];
    const float* cx     = (const float*)d_in[2];
    const float* G      = (const float*)d_in[3];
    const float* wih    = (const float*)d_in[4];
    const float* whh    = (const float*)d_in[5];
    const float* bhh    = (const float*)d_in[6];
    const int*   ntypes = (const int*)d_in[7];
    const int*   tptr   = (const int*)d_in[8];

    float* hy  = (float*)d_out;
    float* cy  = hy + (size_t)B * NN * HH;
    float* gxo = cy + (size_t)B * NN * HH;

    cudaFuncSetAttribute(gates_gemm, cudaFuncAttributeMaxDynamicSharedMemorySize, SM_BYTES);

    void *p_wih, *p_whh, *p_in, *p_hx;
    cudaGetSymbolAddress(&p_wih, g_wih_h);
    cudaGetSymbolAddress(&p_whh, g_whh_h);
    cudaGetSymbolAddress(&p_in,  g_in_h);
    cudaGetSymbolAddress(&p_hx,  g_hx_h);

    cvt_all_kernel<<<CVT_BLOCKS + 1, 256>>>(
        (const float4*)wih, (const float4*)whh, (const float4*)input, (const float4*)hx,
        (uint4*)p_wih, (uint4*)p_whh, (uint4*)p_in, (uint4*)p_hx,
        G, gxo, tptr);

    dim3 grid1(FH / TN, B / TM, NN);   // (16, 4, 21)
    gates_gemm<<<grid1, 512, SM_BYTES>>>(bhh, ntypes, tptr);

    dim3 grid2(HH / 256, B);           // (4, 512)
    pass2<<<grid2, 128>>>(cx, tptr, hy, cy);
}

// round 14
// speedup vs baseline: 1.8012x; 1.2444x over previous
#include <cuda_runtime.h>
#include <cuda_fp16.h>
#include <cstdint>

// ---------------- problem constants ----------------
#define B   512
#define NN  21
#define II  256
#define HH  1024
#define FH  4096          // 4*HH
#define KK  1280          // II + HH
#define EPS 1e-12f

// ---------------- GEMM tiling ----------------
#define TM 128
#define TN 128            // one gate x one 128-h phase block per CTA
#define TK 32
#define NSTAGE 4
#define NCHUNK (KK / TK)
#define PADB 80

#define A_STAGE_B (TM * PADB)          // 10240
#define B_STAGE_B (TN * PADB)          // 10240
#define STAGE_B   (A_STAGE_B + B_STAGE_B)
#define SM_BYTES  (NSTAGE * STAGE_B)   // 81920

// cvt region sizes in 8-element units
#define N8_WIH (5 * FH * II / 8)
#define N8_WHH (5 * FH * HH / 8)
#define N8_IN  (B * NN * II / 8)
#define N8_HX  (B * NN * HH / 8)
#define N8_TOT (N8_WIH + N8_WHH + N8_IN + N8_HX)
#define CVT_BLOCKS ((N8_TOT + 255) / 256)

// ---------------- scratch ----------------
__device__ __half  g_gates_h[(size_t)B * NN * FH];
__device__ __half2 g_gx2[NN * NN];
__device__ __half  g_wih_h[(size_t)5 * FH * II];
__device__ __half  g_whh_h[(size_t)5 * FH * HH];
__device__ __half  g_in_h[(size_t)B * NN * II];
__device__ __half  g_hx_h[(size_t)B * NN * HH];

// ---------------- helpers ----------------
__device__ __forceinline__ uint32_t smem_u32(const void* p) {
    uint32_t a;
    asm("{ .reg .u64 t; cvta.to.shared.u64 t, %1; cvt.u32.u64 %0, t; }" : "=r"(a) : "l"(p));
    return a;
}
__device__ __forceinline__ void cp16(uint32_t saddr, const void* gptr) {
    asm volatile("cp.async.cg.shared.global [%0], [%1], 16;" :: "r"(saddr), "l"(gptr));
}
__device__ __forceinline__ void ldsm4(uint32_t* r, uint32_t saddr) {
    asm volatile("ldmatrix.sync.aligned.m8n8.x4.shared.b16 {%0,%1,%2,%3}, [%4];"
                 : "=r"(r[0]), "=r"(r[1]), "=r"(r[2]), "=r"(r[3]) : "r"(saddr));
}
__device__ __forceinline__ void mma16(float* c, const uint32_t* a, const uint32_t* b) {
    asm volatile(
        "mma.sync.aligned.m16n8k16.row.col.f32.f16.f16.f32 "
        "{%0,%1,%2,%3}, {%4,%5,%6,%7}, {%8,%9}, {%0,%1,%2,%3};"
        : "+f"(c[0]), "+f"(c[1]), "+f"(c[2]), "+f"(c[3])
        : "r"(a[0]), "r"(a[1]), "r"(a[2]), "r"(a[3]), "r"(b[0]), "r"(b[1]));
}
__device__ __forceinline__ float tanh_a(float x) {
    float r;
    asm("tanh.approx.f32 %0, %1;" : "=f"(r) : "f"(x));
    return r;
}
__device__ __forceinline__ float fsig(float x) {
    return fmaf(tanh_a(0.5f * x), 0.5f, 0.5f);
}
__device__ __forceinline__ float phase_of(int h) {
    return floorf((float)h / (float)(HH - 1) * 8.0f + 1.0f);
}
// does the 128-h block starting at h0 contain ANY mask=1 position?
__device__ __forceinline__ bool block_active(int h0, float t1) {
    int p0 = (int)phase_of(h0);
    int h1 = h0 + 127; if (h1 > HH - 1) h1 = HH - 1;
    int p1 = (int)phase_of(h1);
#pragma unroll 2
    for (int p = p0; p <= p1; p++)
        if (fmodf(t1, (float)p) < 0.01f) return true;
    return false;
}

// ---------------- kernel: fused fp32->fp16 conversion + gx normalization ----------------
__global__ void cvt_all_kernel(const float4* __restrict__ wih, const float4* __restrict__ whh,
                               const float4* __restrict__ in,  const float4* __restrict__ hx,
                               uint4* __restrict__ o_wih, uint4* __restrict__ o_whh,
                               uint4* __restrict__ o_in,  uint4* __restrict__ o_hx,
                               const float* __restrict__ G, float* __restrict__ gx_out,
                               const int* __restrict__ tptr) {
    if (blockIdx.x == CVT_BLOCKS) {
        __shared__ float sG[NN * NN];
        __shared__ float den[NN];
        __shared__ float den2[NN];
        int tid = threadIdx.x;
        for (int i = tid; i < NN * NN; i += blockDim.x) sG[i] = G[i];
        __syncthreads();
        if (tid < NN) {
            float s = 0.f;
            for (int j = 0; j < NN; j++) s += fabsf(sG[tid * NN + j]);
            den[tid] = fmaxf(s, EPS);
        }
        __syncthreads();
        for (int i = tid; i < NN * NN; i += blockDim.x) sG[i] = sG[i] / den[i / NN];
        __syncthreads();
        if (tid < NN) {
            float s = 0.f;
            for (int j = 0; j < NN; j++) s += fabsf(sG[tid * NN + j]);
            den2[tid] = fmaxf(s, EPS);
        }
        __syncthreads();
        for (int i = tid; i < NN * NN; i += blockDim.x) {
            float w = sG[i];
            g_gx2[i]  = __float2half2_rn(w);
            gx_out[i] = w / den2[i / NN];
        }
        return;
    }

    int i = blockIdx.x * blockDim.x + threadIdx.x;
    if (i >= N8_TOT) return;
    const float t1 = (float)(*tptr) + 1.0f;
    const float4* s;
    uint4* d;
    int j = i;
    if (j < N8_WIH) {
        int ol = (j >> 5) & (FH - 1);      // II=256 -> 32 j-units per row
        int gate = ol >> 10;
        if (gate != 3 && !block_active((ol & 1023) & ~127, t1)) return;
        s = wih; d = o_wih;
    } else {
        j -= N8_WIH;
        if (j < N8_WHH) {
            int ol = (j >> 7) & (FH - 1);  // HH=1024 -> 128 j-units per row
            int gate = ol >> 10;
            if (gate != 3 && !block_active((ol & 1023) & ~127, t1)) return;
            s = whh; d = o_whh;
        } else {
            j -= N8_WHH;
            if (j < N8_IN) { s = in; d = o_in; }
            else { j -= N8_IN; s = hx; d = o_hx; }
        }
    }
    float4 v0 = s[2 * j];
    float4 v1 = s[2 * j + 1];
    __half2 h0 = __floats2half2_rn(v0.x, v0.y);
    __half2 h1 = __floats2half2_rn(v0.z, v0.w);
    __half2 h2 = __floats2half2_rn(v1.x, v1.y);
    __half2 h3 = __floats2half2_rn(v1.z, v1.w);
    uint4 o;
    o.x = *(uint32_t*)&h0; o.y = *(uint32_t*)&h1;
    o.z = *(uint32_t*)&h2; o.w = *(uint32_t*)&h3;
    d[j] = o;
}

// ---------------- kernel 1: fp16 mma.sync gates GEMM, TN=128, 256 thr, 2 CTA/SM ----------------
__global__ __launch_bounds__(256, 2)
void gates_gemm(const float* __restrict__ bhh, const int* __restrict__ ntypes,
                const int* __restrict__ tptr) {
    const int bo = blockIdx.x * TN;
    {
        const float t1 = (float)(*tptr) + 1.0f;
        const int gate = bo >> 10;
        if (gate != 3 && !block_active(bo & 1023, t1)) return;  // uniform exit
    }

    extern __shared__ char smc[];
    const int tid  = threadIdx.x;
    const int lane = tid & 31;
    const int wid  = tid >> 5;

    const int n  = blockIdx.z;
    const int bm = blockIdx.y * TM;
    const int nt = ntypes[n];
    const __half* wih = g_wih_h + (size_t)nt * FH * II;
    const __half* whh = g_whh_h + (size_t)nt * FH * HH;

    const uint32_t sb = smem_u32(smc);

    // warp tiling: 4 (m) x 2 (n), warp tile 32x64
    const int wm = (wid & 3) * 32;
    const int wn = (wid >> 2) * 64;

    const uint32_t aL = (uint32_t)((((lane >> 3) & 1) * 8 + (lane & 7)) * PADB + (lane >> 4) * 16);
    const uint32_t bL = (uint32_t)((((lane >> 4) & 1) * 8 + (lane & 7)) * PADB + ((lane >> 3) & 1) * 16);

    float acc[2][8][4];
#pragma unroll
    for (int i = 0; i < 2; i++)
#pragma unroll
        for (int j = 0; j < 8; j++)
#pragma unroll
            for (int v = 0; v < 4; v++) acc[i][j][v] = 0.f;

    // ---- stage loader: A 512 chunks, B 512 chunks of 16B; 256 threads ----
    auto load_stage = [&](int kt) {
        const int s  = kt % NSTAGE;
        const int k0 = kt * TK;
        const uint32_t ab = sb + (uint32_t)(s * STAGE_B);
        const uint32_t bb = ab + (uint32_t)A_STAGE_B;
#pragma unroll
        for (int i = 0; i < 2; i++) {
            int f = tid + i * 256;
            int r = f >> 2, c = f & 3;
            int k = k0 + c * 8;
            const __half* src = (k < II)
                ? g_in_h + ((size_t)(bm + r) * NN + n) * II + k
                : g_hx_h + ((size_t)(bm + r) * NN + n) * HH + (k - II);
            cp16(ab + (uint32_t)(r * PADB + c * 16), src);
        }
#pragma unroll
        for (int i = 0; i < 2; i++) {
            int f = tid + i * 256;
            int r = f >> 2, c = f & 3;
            int k = k0 + c * 8;
            const __half* src = (k < II)
                ? wih + (size_t)(bo + r) * II + k
                : whh + (size_t)(bo + r) * HH + (k - II);
            cp16(bb + (uint32_t)(r * PADB + c * 16), src);
        }
    };

#pragma unroll
    for (int s = 0; s < NSTAGE; s++) {
        load_stage(s);
        asm volatile("cp.async.commit_group;" ::: "memory");
    }

    for (int kt = 0; kt < NCHUNK; kt++) {
        asm volatile("cp.async.wait_group %0;" :: "n"(NSTAGE - 1) : "memory");
        __syncthreads();

        const int s = kt % NSTAGE;
        const uint32_t sAb = sb + (uint32_t)(s * STAGE_B);
        const uint32_t sBb = sAb + (uint32_t)A_STAGE_B;

#pragma unroll
        for (int ks = 0; ks < TK / 16; ks++) {
            const uint32_t kb = (uint32_t)(ks * 32);
            uint32_t af[2][4];
#pragma unroll
            for (int mi = 0; mi < 2; mi++)
                ldsm4(af[mi], sAb + (uint32_t)((wm + mi * 16) * PADB) + kb + aL);
            uint32_t bq[4][4];
#pragma unroll
            for (int np = 0; np < 4; np++)
                ldsm4(bq[np], sBb + (uint32_t)((wn + np * 16) * PADB) + kb + bL);
#pragma unroll
            for (int mi = 0; mi < 2; mi++)
#pragma unroll
                for (int ni = 0; ni < 8; ni++)
                    mma16(acc[mi][ni], af[mi], &bq[ni >> 1][(ni & 1) * 2]);
        }
        __syncthreads();
        if (kt + NSTAGE < NCHUNK) load_stage(kt + NSTAGE);
        asm volatile("cp.async.commit_group;" ::: "memory");
    }

    const int lr = lane >> 2;
    const int lq = lane & 3;
    const float* brow = bhh + (size_t)nt * FH + bo;
#pragma unroll
    for (int mi = 0; mi < 2; mi++) {
        int r0 = wm + mi * 16 + lr;
        __half* out0 = g_gates_h + ((size_t)(bm + r0)     * NN + n) * FH + bo;
        __half* out1 = g_gates_h + ((size_t)(bm + r0 + 8) * NN + n) * FH + bo;
#pragma unroll
        for (int ni = 0; ni < 8; ni++) {
            int col = wn + ni * 8 + lq * 2;
            float2 bv = *(const float2*)(brow + col);
            __half2 v0 = __floats2half2_rn(acc[mi][ni][0] + bv.x, acc[mi][ni][1] + bv.y);
            __half2 v1 = __floats2half2_rn(acc[mi][ni][2] + bv.x, acc[mi][ni][3] + bv.y);
            *(__half2*)(out0 + col) = v0;
            *(__half2*)(out1 + col) = v1;
        }
    }
}

// ---------------- kernel 2: graph mix + LSTM; clockwork-mask dead-gate skipping ----------------
__global__ __launch_bounds__(128)
void pass2(const float* __restrict__ cx, const int* __restrict__ tptr,
           float* __restrict__ hy, float* __restrict__ cyo) {
    __shared__ __half2 sgx[NN * NN];
    const int tid = threadIdx.x;
    for (int i = tid; i < NN * NN; i += 128) sgx[i] = g_gx2[i];
    __syncthreads();

    const int b = blockIdx.y;
    const int h = blockIdx.x * 256 + tid * 2;

    const float t1  = (float)(*tptr) + 1.0f;
    const float ph0 = phase_of(h);
    const float ph1 = phase_of(h + 1);
    const float mk0 = (fmodf(t1, ph0) < 0.01f) ? 1.0f : 0.0f;
    const float mk1 = (fmodf(t1, ph1) < 0.01f) ? 1.0f : 0.0f;
    const bool  active = (mk0 + mk1) > 0.f;

    const __half* gbase = g_gates_h + (size_t)b * NN * FH + h;

    __half2 rg3[NN];
#pragma unroll
    for (int nI = 0; nI < NN; nI++)
        rg3[nI] = *(const __half2*)(gbase + (size_t)nI * FH + 3 * HH);

    if (active) {
        __half2 rg0[NN], rg1[NN], rg2[NN];
#pragma unroll
        for (int nI = 0; nI < NN; nI++) {
            const __half* p = gbase + (size_t)nI * FH;
            rg0[nI] = *(const __half2*)(p);
            rg1[nI] = *(const __half2*)(p + HH);
            rg2[nI] = *(const __half2*)(p + 2 * HH);
        }
#pragma unroll 1
        for (int m = 0; m < NN; m++) {
            const __half2* wrow = &sgx[m * NN];
            __half2 z = __float2half2_rn(0.f);
            __half2 i0 = z, i1 = z, f0 = z, f1 = z, c0 = z, c1 = z, o0 = z, o1 = z;
#pragma unroll
            for (int nI = 0; nI < NN; nI++) {
                __half2 w = wrow[nI];
                if (nI & 1) {
                    i1 = __hfma2(w, rg0[nI], i1);
                    f1 = __hfma2(w, rg1[nI], f1);
                    c1 = __hfma2(w, rg2[nI], c1);
                    o1 = __hfma2(w, rg3[nI], o1);
                } else {
                    i0 = __hfma2(w, rg0[nI], i0);
                    f0 = __hfma2(w, rg1[nI], f0);
                    c0 = __hfma2(w, rg2[nI], c0);
                    o0 = __hfma2(w, rg3[nI], o0);
                }
            }
            float2 ig = __half22float2(__hadd2(i0, i1));
            float2 fg = __half22float2(__hadd2(f0, f1));
            float2 cg = __half22float2(__hadd2(c0, c1));
            float2 og = __half22float2(__hadd2(o0, o1));

            size_t idx = ((size_t)b * NN + m) * HH + h;
            float2 cxv = *(const float2*)(cx + idx);

            float isx = fsig(ig.x), isy = fsig(ig.y);
            float fsx = fsig(fg.x), fsy = fsig(fg.y);
            float ctx = tanh_a(cg.x), cty = tanh_a(cg.y);
            float osx = fsig(og.x), osy = fsig(og.y);

            float cyx = mk0 * (fsx * cxv.x + isx * ctx) + (1.0f - mk0) * cxv.x;
            float cyy = mk1 * (fsy * cxv.y + isy * cty) + (1.0f - mk1) * cxv.y;
            float hyx = osx * tanh_a(cyx);
            float hyy = osy * tanh_a(cyy);

            *(float2*)(hy + idx)  = make_float2(hyx, hyy);
            *(float2*)(cyo + idx) = make_float2(cyx, cyy);
        }
    } else {
#pragma unroll 1
        for (int m = 0; m < NN; m++) {
            const __half2* wrow = &sgx[m * NN];
            __half2 z = __float2half2_rn(0.f);
            __half2 o0 = z, o1 = z;
#pragma unroll
            for (int nI = 0; nI < NN; nI++) {
                __half2 w = wrow[nI];
                if (nI & 1) o1 = __hfma2(w, rg3[nI], o1);
                else        o0 = __hfma2(w, rg3[nI], o0);
            }
            float2 og = __half22float2(__hadd2(o0, o1));

            size_t idx = ((size_t)b * NN + m) * HH + h;
            float2 cxv = *(const float2*)(cx + idx);

            float hyx = fsig(og.x) * tanh_a(cxv.x);
            float hyy = fsig(og.y) * tanh_a(cxv.y);

            *(float2*)(hy + idx)  = make_float2(hyx, hyy);
            *(float2*)(cyo + idx) = cxv;
        }
    }
}

// ---------------- launch ----------------
extern "C" void kernel_launch(void* const* d_in, const int* in_sizes, int n_in,
                              void* d_out, int out_size) {
    const float* input  = (const float*)d_in[0];
    const float* hx     = (const float*)d_in[1];
    const float* cx     = (const float*)d_in[2];
    const float* G      = (const float*)d_in[3];
    const float* wih    = (const float*)d_in[4];
    const float* whh    = (const float*)d_in[5];
    const float* bhh    = (const float*)d_in[6];
    const int*   ntypes = (const int*)d_in[7];
    const int*   tptr   = (const int*)d_in[8];

    float* hy  = (float*)d_out;
    float* cy  = hy + (size_t)B * NN * HH;
    float* gxo = cy + (size_t)B * NN * HH;

    cudaFuncSetAttribute(gates_gemm, cudaFuncAttributeMaxDynamicSharedMemorySize, SM_BYTES);

    void *p_wih, *p_whh, *p_in, *p_hx;
    cudaGetSymbolAddress(&p_wih, g_wih_h);
    cudaGetSymbolAddress(&p_whh, g_whh_h);
    cudaGetSymbolAddress(&p_in,  g_in_h);
    cudaGetSymbolAddress(&p_hx,  g_hx_h);

    cvt_all_kernel<<<CVT_BLOCKS + 1, 256>>>(
        (const float4*)wih, (const float4*)whh, (const float4*)input, (const float4*)hx,
        (uint4*)p_wih, (uint4*)p_whh, (uint4*)p_in, (uint4*)p_hx,
        G, gxo, tptr);

    dim3 grid1(FH / TN, B / TM, NN);   // (32, 4, 21)
    gates_gemm<<<grid1, 256, SM_BYTES>>>(bhh, ntypes, tptr);

    dim3 grid2(HH / 256, B);           // (4, 512)
    pass2<<<grid2, 128>>>(cx, tptr, hy, cy);
}